// round 2
// baseline (speedup 1.0000x reference)
#include <cuda_runtime.h>

#define K_CAPS 10
#define B_SZ   256
#define N_IN   1152
#define IC     8
#define OC     16

// 10*256*1152*16 floats = 188.7 MB scratch for u_hat, layout [k][b][n][o]
__device__ float g_uhat[(size_t)K_CAPS * B_SZ * N_IN * OC];

// ---------------------------------------------------------------------------
// Kernel 1: u_hat[k,b,n,:] = u[b,n,:] @ W[k,n,:,:]
// grid: (N/64, B/64, K) = (18, 4, 10); 256 threads.
// thread: q = tid&3 (o-quad: columns 4q..4q+3), nl = tid>>2 (n within tile).
// W slice (32 floats) cached in registers across the whole 64-b loop.
// Warp STG pattern: 8 n x 4 q float4 = 512B contiguous (fully coalesced).
// ---------------------------------------------------------------------------
__global__ __launch_bounds__(256) void uhat_kernel(const float* __restrict__ u,
                                                   const float* __restrict__ W) {
    const int q  = threadIdx.x & 3;
    const int nl = threadIdx.x >> 2;
    const int n  = blockIdx.x * 64 + nl;
    const int b0 = blockIdx.y * 64;
    const int k  = blockIdx.z;

    // W[k][n][i][4q..4q+3], i = 0..7  -> 8 float4 in registers
    const float4* Wv = reinterpret_cast<const float4*>(
        W + ((size_t)k * N_IN + n) * (IC * OC)) + q;
    float4 wr[8];
#pragma unroll
    for (int i = 0; i < 8; i++) wr[i] = __ldg(Wv + i * 4);  // +16 floats per i

    const float4* uv   = reinterpret_cast<const float4*>(u);
    float4*       outv = reinterpret_cast<float4*>(g_uhat);

#pragma unroll 4
    for (int bb = 0; bb < 64; bb++) {
        const int b = b0 + bb;
        const size_t ui = ((size_t)b * N_IN + n) * 2;   // 8 floats = 2 float4
        const float4 ua = __ldg(uv + ui);
        const float4 ub = __ldg(uv + ui + 1);
        const float uu[8] = {ua.x, ua.y, ua.z, ua.w, ub.x, ub.y, ub.z, ub.w};

        float4 acc = make_float4(0.f, 0.f, 0.f, 0.f);
#pragma unroll
        for (int i = 0; i < 8; i++) {
            acc.x = fmaf(uu[i], wr[i].x, acc.x);
            acc.y = fmaf(uu[i], wr[i].y, acc.y);
            acc.z = fmaf(uu[i], wr[i].z, acc.z);
            acc.w = fmaf(uu[i], wr[i].w, acc.w);
        }
        outv[(((size_t)k * B_SZ + b) * N_IN + n) * 4 + q] = acc;
    }
}

// ---------------------------------------------------------------------------
// Kernel 2: dynamic routing, one CTA per (k,b). 384 threads, 3 n-rows each.
// b_ij is identical across out_c (broadcast add), so it is a per-n scalar.
// Rows are re-read via L1 (72KB/CTA resident); no smem tile needed.
// ---------------------------------------------------------------------------
__global__ __launch_bounds__(384) void routing_kernel(float* __restrict__ out) {
    const int kb  = blockIdx.x;                       // 0..2559 = k*256+b
    const float* uh = g_uhat + (size_t)kb * (N_IN * OC);
    const int t    = threadIdx.x;
    const int wid  = t >> 5;
    const int lane = t & 31;

    __shared__ float sred[12];        // per-warp scalar partials
    __shared__ float sbc;             // broadcast scalar
    __shared__ float sjoint[12][17];  // per-warp [acc0..15, esum]
    __shared__ float sv[16];          // v_j broadcast

    float blog[3] = {0.f, 0.f, 0.f};

    for (int it = 0; it < 3; it++) {
        float w[3];
        float esum = 0.f;
        if (it == 0) {
            w[0] = w[1] = w[2] = 1.f;                 // softmax(0) handled via invZ
        } else {
            // block max of blog
            float m = fmaxf(blog[0], fmaxf(blog[1], blog[2]));
#pragma unroll
            for (int off = 16; off; off >>= 1)
                m = fmaxf(m, __shfl_xor_sync(0xffffffffu, m, off));
            if (lane == 0) sred[wid] = m;
            __syncthreads();
            if (t == 0) {
                float mm = sred[0];
#pragma unroll
                for (int i = 1; i < 12; i++) mm = fmaxf(mm, sred[i]);
                sbc = mm;
            }
            __syncthreads();
            m = sbc;
#pragma unroll
            for (int j = 0; j < 3; j++) {
                w[j] = __expf(blog[j] - m);
                esum += w[j];
            }
        }

        // partial s accumulation over this thread's 3 rows
        float acc[16];
#pragma unroll
        for (int o = 0; o < 16; o++) acc[o] = 0.f;
#pragma unroll
        for (int j = 0; j < 3; j++) {
            const int n = t + 384 * j;
            const float4* r = reinterpret_cast<const float4*>(uh + n * OC);
            const float4 r0 = __ldg(r + 0);
            const float4 r1 = __ldg(r + 1);
            const float4 r2 = __ldg(r + 2);
            const float4 r3 = __ldg(r + 3);
            const float wj = w[j];
            acc[0]  = fmaf(wj, r0.x, acc[0]);  acc[1]  = fmaf(wj, r0.y, acc[1]);
            acc[2]  = fmaf(wj, r0.z, acc[2]);  acc[3]  = fmaf(wj, r0.w, acc[3]);
            acc[4]  = fmaf(wj, r1.x, acc[4]);  acc[5]  = fmaf(wj, r1.y, acc[5]);
            acc[6]  = fmaf(wj, r1.z, acc[6]);  acc[7]  = fmaf(wj, r1.w, acc[7]);
            acc[8]  = fmaf(wj, r2.x, acc[8]);  acc[9]  = fmaf(wj, r2.y, acc[9]);
            acc[10] = fmaf(wj, r2.z, acc[10]); acc[11] = fmaf(wj, r2.w, acc[11]);
            acc[12] = fmaf(wj, r3.x, acc[12]); acc[13] = fmaf(wj, r3.y, acc[13]);
            acc[14] = fmaf(wj, r3.z, acc[14]); acc[15] = fmaf(wj, r3.w, acc[15]);
        }

        // fused warp reduction of 16 accs + esum
#pragma unroll
        for (int off = 16; off; off >>= 1) {
#pragma unroll
            for (int o = 0; o < 16; o++)
                acc[o] += __shfl_xor_sync(0xffffffffu, acc[o], off);
            esum += __shfl_xor_sync(0xffffffffu, esum, off);
        }
        if (lane == 0) {
#pragma unroll
            for (int o = 0; o < 16; o++) sjoint[wid][o] = acc[o];
            sjoint[wid][16] = esum;
        }
        __syncthreads();

        // warp 0: final cross-warp reduce, squash, broadcast / output
        if (wid == 0) {
            float val = 0.f;
            if (lane < 17) {
#pragma unroll
                for (int ww = 0; ww < 12; ww++) val += sjoint[ww][lane];
            }
            const float Z = __shfl_sync(0xffffffffu, val, 16);
            const float invZ = (it == 0) ? (1.f / (float)N_IN) : (1.f / Z);
            float s = (lane < 16) ? val * invZ : 0.f;
            float sq = s * s;
#pragma unroll
            for (int off = 8; off; off >>= 1)
                sq += __shfl_xor_sync(0xffffffffu, sq, off);
            const float scale = sqrtf(sq) / (1.f + sq);   // squash factor
            const float v = s * scale;
            if (lane < 16) {
                if (it == 2) out[(size_t)kb * OC + lane] = v;
                else         sv[lane] = v;
            }
        }
        __syncthreads();

        if (it < 2) {
            // a-pass: blog[j] += <u_hat row, v>
#pragma unroll
            for (int j = 0; j < 3; j++) {
                const int n = t + 384 * j;
                const float4* r = reinterpret_cast<const float4*>(uh + n * OC);
                const float4 r0 = __ldg(r + 0);
                const float4 r1 = __ldg(r + 1);
                const float4 r2 = __ldg(r + 2);
                const float4 r3 = __ldg(r + 3);
                float d = r0.x * sv[0] + r0.y * sv[1] + r0.z * sv[2] + r0.w * sv[3];
                d = fmaf(r1.x, sv[4],  fmaf(r1.y, sv[5],  fmaf(r1.z, sv[6],  fmaf(r1.w, sv[7],  d))));
                d = fmaf(r2.x, sv[8],  fmaf(r2.y, sv[9],  fmaf(r2.z, sv[10], fmaf(r2.w, sv[11], d))));
                d = fmaf(r3.x, sv[12], fmaf(r3.y, sv[13], fmaf(r3.z, sv[14], fmaf(r3.w, sv[15], d))));
                blog[j] += d;
            }
        }
    }
}

// ---------------------------------------------------------------------------
extern "C" void kernel_launch(void* const* d_in, const int* in_sizes, int n_in,
                              void* d_out, int out_size) {
    const float* u = (const float*)d_in[0];
    const float* W = (const float*)d_in[1];
    // Robust to input ordering: W has 10*1152*8*16 = 1474560 elements.
    if (in_sizes[0] == K_CAPS * N_IN * IC * OC) {
        W = (const float*)d_in[0];
        u = (const float*)d_in[1];
    }
    uhat_kernel<<<dim3(N_IN / 64, B_SZ / 64, K_CAPS), 256>>>(u, W);
    routing_kernel<<<K_CAPS * B_SZ, 384>>>((float*)d_out);
}

// round 3
// speedup vs baseline: 1.7265x; 1.7265x over previous
#include <cuda_runtime.h>

#define K_CAPS 10
#define B_SZ   256
#define N_IN   1152
#define IC     8
#define OC     16

// 10*256*1152*16 floats = 188.7 MB scratch for u_hat, layout [k][b][n][o]
__device__ float g_uhat[(size_t)K_CAPS * B_SZ * N_IN * OC];

// ---------------------------------------------------------------------------
// Kernel 1: u_hat[k,b,n,:] = u[b,n,:] @ W[k,n,:,:]   (unchanged from R2)
// ---------------------------------------------------------------------------
__global__ __launch_bounds__(256) void uhat_kernel(const float* __restrict__ u,
                                                   const float* __restrict__ W) {
    const int q  = threadIdx.x & 3;
    const int nl = threadIdx.x >> 2;
    const int n  = blockIdx.x * 64 + nl;
    const int b0 = blockIdx.y * 64;
    const int k  = blockIdx.z;

    const float4* Wv = reinterpret_cast<const float4*>(
        W + ((size_t)k * N_IN + n) * (IC * OC)) + q;
    float4 wr[8];
#pragma unroll
    for (int i = 0; i < 8; i++) wr[i] = __ldg(Wv + i * 4);

    const float4* uv   = reinterpret_cast<const float4*>(u);
    float4*       outv = reinterpret_cast<float4*>(g_uhat);

#pragma unroll 4
    for (int bb = 0; bb < 64; bb++) {
        const int b = b0 + bb;
        const size_t ui = ((size_t)b * N_IN + n) * 2;
        const float4 ua = __ldg(uv + ui);
        const float4 ub = __ldg(uv + ui + 1);
        const float uu[8] = {ua.x, ua.y, ua.z, ua.w, ub.x, ub.y, ub.z, ub.w};

        float4 acc = make_float4(0.f, 0.f, 0.f, 0.f);
#pragma unroll
        for (int i = 0; i < 8; i++) {
            acc.x = fmaf(uu[i], wr[i].x, acc.x);
            acc.y = fmaf(uu[i], wr[i].y, acc.y);
            acc.z = fmaf(uu[i], wr[i].z, acc.z);
            acc.w = fmaf(uu[i], wr[i].w, acc.w);
        }
        outv[(((size_t)k * B_SZ + b) * N_IN + n) * 4 + q] = acc;
    }
}

// ---------------------------------------------------------------------------
// Kernel 2 v2: routing with register-resident u_hat, quarter-row layout.
// One CTA per (k,b), 384 threads, 2 CTAs/SM.
// lane = 4*rsub + q: thread owns o-quad q of rows 8*(wid*12+s)+rsub, s=0..11.
// All 5 data passes run from registers; global read happens exactly once,
// fully coalesced (each warp LDG.128 = 512B contiguous).
// ---------------------------------------------------------------------------
__global__ __launch_bounds__(384, 2) void routing_kernel(float* __restrict__ out) {
    const int kb   = blockIdx.x;                      // k*256 + b
    const float4* uh = reinterpret_cast<const float4*>(g_uhat)
                       + (size_t)kb * (N_IN * 4);
    const int t    = threadIdx.x;
    const int wid  = t >> 5;
    const int lane = t & 31;
    const int q    = lane & 3;       // o-quad: columns 4q..4q+3
    const int rsub = lane >> 2;      // row within 8-row group

    __shared__ float sj[12][20];     // [warp][o(0..15), esum] (padded)
    __shared__ float sv[16];         // v_j broadcast
    __shared__ float sred[12];       // per-warp max partials
    __shared__ float sbc;            // block max broadcast

    // ---- one-time load: 12 coalesced LDG.128 per thread ----
    float4 r[12];
#pragma unroll
    for (int s = 0; s < 12; s++) {
        const int n = 8 * (wid * 12 + s) + rsub;
        r[s] = __ldg(uh + n * 4 + q);
    }
    float blog[12];
#pragma unroll
    for (int s = 0; s < 12; s++) blog[s] = 0.f;

    for (int it = 0; it < 3; it++) {
        // ---- s-pass: weighted accumulate into this thread's o-quad ----
        float4 acc = make_float4(0.f, 0.f, 0.f, 0.f);
        float esum = 0.f;
        if (it == 0) {
#pragma unroll
            for (int s = 0; s < 12; s++) {
                acc.x += r[s].x; acc.y += r[s].y;
                acc.z += r[s].z; acc.w += r[s].w;
            }
        } else {
            const float m = sbc;
#pragma unroll
            for (int s = 0; s < 12; s++) {
                const float w = __expf(blog[s] - m);
                esum += (q == 0) ? w : 0.f;   // count each row once
                acc.x = fmaf(w, r[s].x, acc.x);
                acc.y = fmaf(w, r[s].y, acc.y);
                acc.z = fmaf(w, r[s].z, acc.z);
                acc.w = fmaf(w, r[s].w, acc.w);
            }
        }
        // reduce over lanes sharing the same q (offsets 4,8,16); esum rides along
#pragma unroll
        for (int off = 4; off <= 16; off <<= 1) {
            acc.x += __shfl_xor_sync(0xffffffffu, acc.x, off);
            acc.y += __shfl_xor_sync(0xffffffffu, acc.y, off);
            acc.z += __shfl_xor_sync(0xffffffffu, acc.z, off);
            acc.w += __shfl_xor_sync(0xffffffffu, acc.w, off);
            esum  += __shfl_xor_sync(0xffffffffu, esum,  off);
        }
        if (lane < 4) {                       // lanes 0..3 hold o = 4q..4q+3
            sj[wid][4 * q + 0] = acc.x;
            sj[wid][4 * q + 1] = acc.y;
            sj[wid][4 * q + 2] = acc.z;
            sj[wid][4 * q + 3] = acc.w;
        }
        if (lane == 0) sj[wid][16] = esum;
        __syncthreads();

        // ---- warp 0: cross-warp reduce (17 values x 12 warps), squash ----
        if (wid == 0) {
            float val = 0.f;
            if (lane < 17) {
#pragma unroll
                for (int ww = 0; ww < 12; ww++) val += sj[ww][lane];
            }
            const float Z = __shfl_sync(0xffffffffu, val, 16);
            const float invZ = (it == 0) ? (1.f / (float)N_IN) : (1.f / Z);
            float s_ = (lane < 16) ? val * invZ : 0.f;
            float sq = s_ * s_;
#pragma unroll
            for (int off = 8; off; off >>= 1)
                sq += __shfl_xor_sync(0xffffffffu, sq, off);
            const float scale = sqrtf(sq) / (1.f + sq);   // squash factor
            const float v = s_ * scale;
            if (lane < 16) {
                if (it == 2) out[(size_t)kb * OC + lane] = v;
                else         sv[lane] = v;
            }
        }
        __syncthreads();

        // ---- a-pass + block max (iterations 0,1 only) ----
        if (it < 2) {
            const float4 vq = reinterpret_cast<const float4*>(sv)[q];
            float mymax = -3.402823466e+38f;
#pragma unroll
            for (int s = 0; s < 12; s++) {
                float d = r[s].x * vq.x;
                d = fmaf(r[s].y, vq.y, d);
                d = fmaf(r[s].z, vq.z, d);
                d = fmaf(r[s].w, vq.w, d);
                // sum over the 4 q-lanes of this row (bit-identical on all 4)
                d += __shfl_xor_sync(0xffffffffu, d, 1);
                d += __shfl_xor_sync(0xffffffffu, d, 2);
                blog[s] += d;
                mymax = fmaxf(mymax, blog[s]);
            }
            // block max of blog for next iteration's softmax
#pragma unroll
            for (int off = 16; off; off >>= 1)
                mymax = fmaxf(mymax, __shfl_xor_sync(0xffffffffu, mymax, off));
            if (lane == 0) sred[wid] = mymax;
            __syncthreads();
            if (t == 0) {
                float mm = sred[0];
#pragma unroll
                for (int i = 1; i < 12; i++) mm = fmaxf(mm, sred[i]);
                sbc = mm;
            }
            __syncthreads();
        }
    }
}

// ---------------------------------------------------------------------------
extern "C" void kernel_launch(void* const* d_in, const int* in_sizes, int n_in,
                              void* d_out, int out_size) {
    const float* u = (const float*)d_in[0];
    const float* W = (const float*)d_in[1];
    if (in_sizes[0] == K_CAPS * N_IN * IC * OC) {   // robust to input ordering
        W = (const float*)d_in[0];
        u = (const float*)d_in[1];
    }
    uhat_kernel<<<dim3(N_IN / 64, B_SZ / 64, K_CAPS), 256>>>(u, W);
    routing_kernel<<<K_CAPS * B_SZ, 384>>>((float*)d_out);
}